// round 2
// baseline (speedup 1.0000x reference)
#include <cuda_runtime.h>

// ============================================================================
// PGALoss — analytically reduced.
// For embedded PGA points P,Q:  gp(P,Q) = -1 + (q-p)_x e01 + (q-p)_y e02 + (q-p)_z e03
//   => ||gp|| = sqrt(1+d^2);  ||dual(P-Q)|| = d   (e123 parts cancel)
//   loss_dir = clip((mean[sqrt(1+d^2)+d] - 1)/2, 0, 1),  d = NN distance
//   out = 0.5*(loss_dir0 + loss_dir1)
// Heavy part: brute-force 1-NN, 2 dirs x 2 batches x 8192 x 8192 pairs,
// done with packed fma.rn.f32x2 (FFMA2): 2 candidates per fma chain.
// ============================================================================

#define NPTS     8192
#define NB       2
#define NDIR     2
#define THREADS  128
#define QPT      4                    // queries per thread
#define QPB      (THREADS * QPT)      // 512 queries per block
#define QCHUNKS  (NPTS / QPB)         // 16
#define TILE     512                  // candidates per smem tile
#define CCHUNKS  (NPTS / TILE)        // 16
#define NQ_TOTAL (NDIR * NB * NPTS)   // 32768

typedef unsigned long long ull_t;

#define FMA2(d, a, b, c) \
    asm("fma.rn.f32x2 %0, %1, %2, %3;" : "=l"(d) : "l"(a), "l"(b), "l"(c))

#define PACK2(d, lo, hi) \
    asm("mov.b64 %0, {%1, %2};" : "=l"(d) : "r"(__float_as_uint(lo)), "r"(__float_as_uint(hi)))

#define UNPACK2(lo, hi, v) do {                                   \
    unsigned int _ulo, _uhi;                                      \
    asm("mov.b64 {%0, %1}, %2;" : "=r"(_ulo), "=r"(_uhi) : "l"(v)); \
    lo = __uint_as_float(_ulo); hi = __uint_as_float(_uhi);       \
} while (0)

// Scratch: per-query min squared distance, monotonic uint bits (d2 >= 0).
__device__ unsigned int g_min[NQ_TOTAL];

__global__ void init_kernel() {
    int i = blockIdx.x * blockDim.x + threadIdx.x;
    if (i < NQ_TOTAL) g_min[i] = 0x7F800000u;   // +inf
}

__global__ __launch_bounds__(THREADS, 8)
void nn_kernel(const float* __restrict__ src, const float* __restrict__ tgt) {
    int bid = blockIdx.x;
    int cc  = bid & (CCHUNKS - 1);  bid >>= 4;   // log2(CCHUNKS)=4
    int qc  = bid & (QCHUNKS - 1);  bid >>= 4;   // log2(QCHUNKS)=4
    int b   = bid & 1;
    int dir = bid >> 1;

    const float* qry  = (dir == 0) ? src : tgt;
    const float* cand = (dir == 0) ? tgt : src;
    qry  += (size_t)b * NPTS * 3;
    cand += (size_t)b * NPTS * 3;

    // SoA candidate tile; ull slots hold two consecutive candidates' component
    // -> one LDS.64 yields a ready-made f32x2 candidate pair. 8 KB total.
    __shared__ ull_t sx[TILE / 2], sy[TILE / 2], sz[TILE / 2], sw[TILE / 2];
    float* fx = (float*)sx;
    float* fy = (float*)sy;
    float* fz = (float*)sz;
    float* fw = (float*)sw;

    const int tid = threadIdx.x;

    for (int j = tid; j < TILE; j += THREADS) {
        int ci = cc * TILE + j;
        float x = cand[ci * 3 + 0];
        float y = cand[ci * 3 + 1];
        float z = cand[ci * 3 + 2];
        fx[j] = x; fy[j] = y; fz[j] = z;
        fw[j] = fmaf(x, x, fmaf(y, y, z * z));   // |p|^2
    }
    __syncthreads();

    // Per-thread queries: packed broadcast constants (-2qx,-2qx), etc.
    ull_t qx2[QPT], qy2[QPT], qz2[QPT];
    float q2[QPT], mn[QPT];
#pragma unroll
    for (int k = 0; k < QPT; k++) {
        int qi = qc * QPB + k * THREADS + tid;
        float x = qry[qi * 3 + 0];
        float y = qry[qi * 3 + 1];
        float z = qry[qi * 3 + 2];
        float mx = -2.0f * x, my = -2.0f * y, mz = -2.0f * z;
        PACK2(qx2[k], mx, mx);
        PACK2(qy2[k], my, my);
        PACK2(qz2[k], mz, mz);
        q2[k] = fmaf(x, x, fmaf(y, y, z * z));
        mn[k] = 3.4e38f;
    }

    // Main loop: per candidate-pair x 4 queries = 12 FFMA2 + 8 FMNMX + 4 LDS.64.
    // score(q, p) = |p|^2 - 2 q.p  (min over p; +|q|^2 deferred to the end)
#pragma unroll 2
    for (int j = 0; j < TILE / 2; j++) {
        ull_t cx = sx[j], cy = sy[j], cz = sz[j], cw = sw[j];
#pragma unroll
        for (int k = 0; k < QPT; k++) {
            ull_t s;
            FMA2(s, qz2[k], cz, cw);
            FMA2(s, qy2[k], cy, s);
            FMA2(s, qx2[k], cx, s);
            float lo, hi;
            UNPACK2(lo, hi, s);
            mn[k] = fminf(mn[k], fminf(lo, hi));
        }
    }

#pragma unroll
    for (int k = 0; k < QPT; k++) {
        int qi = qc * QPB + k * THREADS + tid;
        float d2 = fmaxf(mn[k] + q2[k], 0.0f);   // clamp cancellation
        unsigned int* slot = &g_min[((size_t)(dir * NB + b)) * NPTS + qi];
        atomicMin(slot, __float_as_uint(d2));    // exact, order-independent
    }
}

__global__ void reduce_kernel(float* __restrict__ out) {
    __shared__ float s0[1024];
    __shared__ float s1[1024];
    const int tid = threadIdx.x;

    float a0 = 0.0f, a1 = 0.0f;
    for (int i = tid; i < NB * NPTS; i += 1024) {
        float d2 = __uint_as_float(g_min[i]);
        a0 += sqrtf(1.0f + d2) + sqrtf(d2);
        float e2 = __uint_as_float(g_min[NB * NPTS + i]);
        a1 += sqrtf(1.0f + e2) + sqrtf(e2);
    }
    s0[tid] = a0;
    s1[tid] = a1;
    __syncthreads();

    for (int off = 512; off > 0; off >>= 1) {
        if (tid < off) { s0[tid] += s0[tid + off]; s1[tid] += s1[tid + off]; }
        __syncthreads();
    }

    if (tid == 0) {
        const float inv = 1.0f / (float)(NB * NPTS);
        float l0 = (s0[0] * inv - 1.0f) * 0.5f;
        float l1 = (s1[0] * inv - 1.0f) * 0.5f;
        l0 = fminf(fmaxf(l0, 0.0f), 1.0f);
        l1 = fminf(fmaxf(l1, 0.0f), 1.0f);
        out[0] = 0.5f * (l0 + l1);
    }
}

extern "C" void kernel_launch(void* const* d_in, const int* in_sizes, int n_in,
                              void* d_out, int out_size) {
    const float* src = (const float*)d_in[0];   // source_points (2,8192,3) f32
    const float* tgt = (const float*)d_in[1];   // target_points (2,8192,3) f32
    (void)in_sizes; (void)n_in; (void)out_size;

    init_kernel<<<(NQ_TOTAL + 255) / 256, 256>>>();
    nn_kernel<<<NDIR * NB * QCHUNKS * CCHUNKS, THREADS>>>(src, tgt);
    reduce_kernel<<<1, 1024>>>((float*)d_out);
}